// round 1
// baseline (speedup 1.0000x reference)
#include <cuda_runtime.h>
#include <math.h>

#define BB 128
#define TT 256
#define HH 512
#define H3 1536

// ---------------- scratch (module globals: allowed; no cudaMalloc) ----------
__device__ float g_xp[(size_t)BB * TT * H3];   // per-layer input projections (201 MB)
__device__ float g_y [(size_t)BB * TT * HH];   // inter-layer sequence buffer (67 MB)
__device__ float g_h [2][BB * HH];             // ping-pong hidden state
__device__ unsigned g_bar[4];                  // per-batch-group barrier counters

// ---------------- init: zero h0 and barrier counters (every replay) ---------
__global__ void init_k() {
    int i = blockIdx.x * blockDim.x + threadIdx.x;
    if (i < BB * HH) g_h[0][i] = 0.0f;
    if (i < 4) g_bar[i] = 0u;
}

// ---------------- input projection: g_xp = Ain @ Wk + b0 --------------------
// M=B*T=32768, N=3H=1536, K=H=512. 64x64 tile, BK=16, 256 threads, 4x4 micro.
__global__ void __launch_bounds__(256) proj_k(const float* __restrict__ xin,
                                              const float* __restrict__ Wk,
                                              const float* __restrict__ bias,
                                              int useY)
{
    const float* Ain = useY ? (const float*)g_y : xin;
    __shared__ float As[16 * 68];   // As[k][m], padded rows (16B aligned)
    __shared__ float Bs[16 * 68];   // Bs[k][n]
    const int tid = threadIdx.x;
    const int m0 = blockIdx.y * 64;
    const int n0 = blockIdx.x * 64;
    const int tx = tid & 15, ty = tid >> 4;
    const int mA = tid >> 2, kA = (tid & 3) << 2;
    const int kB = tid >> 4, nB = (tid & 15) << 2;
    const float* aptr = Ain + (size_t)(m0 + mA) * HH + kA;
    const float* bptr = Wk + (size_t)kB * H3 + n0 + nB;

    float acc[4][4] = {};
    for (int kt = 0; kt < HH / 16; ++kt) {
        float4 av = *(const float4*)(aptr + kt * 16);
        float4 bv = *(const float4*)(bptr + (size_t)(kt * 16) * H3);
        __syncthreads();
        As[(kA + 0) * 68 + mA] = av.x;
        As[(kA + 1) * 68 + mA] = av.y;
        As[(kA + 2) * 68 + mA] = av.z;
        As[(kA + 3) * 68 + mA] = av.w;
        *(float4*)&Bs[kB * 68 + nB] = bv;
        __syncthreads();
#pragma unroll
        for (int k = 0; k < 16; ++k) {
            float4 a4 = *(const float4*)&As[k * 68 + (ty << 2)];
            float4 b4 = *(const float4*)&Bs[k * 68 + (tx << 2)];
            float aa[4] = {a4.x, a4.y, a4.z, a4.w};
            float bb[4] = {b4.x, b4.y, b4.z, b4.w};
#pragma unroll
            for (int i = 0; i < 4; ++i)
#pragma unroll
                for (int j = 0; j < 4; ++j)
                    acc[i][j] += aa[i] * bb[j];
        }
    }
    float4 b4 = *(const float4*)&bias[n0 + (tx << 2)];
    float bbv[4] = {b4.x, b4.y, b4.z, b4.w};
#pragma unroll
    for (int i = 0; i < 4; ++i) {
        int row = m0 + (ty << 2) + i;
        float4 o;
        o.x = acc[i][0] + bbv[0];
        o.y = acc[i][1] + bbv[1];
        o.z = acc[i][2] + bbv[2];
        o.w = acc[i][3] + bbv[3];
        *(float4*)&g_xp[(size_t)row * H3 + n0 + (tx << 2)] = o;
    }
}

// ---------------- persistent recurrent kernel (one per layer) ---------------
// Grid: 128 CTAs = 4 batch-groups (32 batches) x 32 h-groups (16 h-cols).
// Each CTA keeps its Wu slice [512][48] in smem for all 256 steps.
// Per step: group barrier -> stage h slice -> 32x48 GEMM -> gates -> write h/y.
#define SM_WS   (512 * 48)        // weights  (24576 floats)
#define SM_HS   (32 * 513)        // staged h (padded rows)
#define SM_RECS (32 * 49)         // rec pre-activations
#define SM_BRS  48
#define SMEM_FLOATS (SM_WS + SM_HS + SM_RECS + SM_BRS)

__global__ void __launch_bounds__(128, 1) gru_layer_k(const float* __restrict__ Wu,
                                                      const float* __restrict__ br,
                                                      float* __restrict__ dout,
                                                      int layer, int isLast)
{
    extern __shared__ float sm[];
    float* ws   = sm;                       // [k][j], j = gate*16 + cc
    float* hs   = ws + SM_WS;               // [b][k] (row stride 513)
    float* recs = hs + SM_HS;               // [b][j] (row stride 49)
    float* brs  = recs + SM_RECS;

    const int tid = threadIdx.x;
    const int g   = blockIdx.x >> 5;        // batch group 0..3
    const int hg  = blockIdx.x & 31;        // h group 0..31
    const int b0g = g * 32;
    const int c0g = hg * 16;

    // one-time: load Wu slice + recurrent bias slice into smem
    for (int idx = tid; idx < SM_WS; idx += 128) {
        int k = idx / 48, j = idx % 48;
        int gate = j >> 4, cc = j & 15;
        ws[idx] = Wu[(size_t)k * H3 + gate * HH + c0g + cc];
    }
    for (int j = tid; j < 48; j += 128) {
        int gate = j >> 4, cc = j & 15;
        brs[j] = br[gate * HH + c0g + cc];
    }
    __syncthreads();

    const int rt = tid & 7, ct = tid >> 3;   // 8 x 16 thread grid
    const int r0 = rt * 4;                   // 4 batch rows / thread
    const int c0 = ct * 3;                   // 3 cols / thread
    const unsigned layerBase = (unsigned)layer * TT;

    for (int t = 0; t < TT; ++t) {
        // ---- inter-CTA barrier (per batch group, monotonic counter) ----
        unsigned target = 32u * (layerBase + (unsigned)t);
        if (tid == 0) {
            while (*(volatile unsigned*)&g_bar[g] < target) { }
        }
        __syncthreads();
        __threadfence();

        // ---- stage h[b0g..b0g+31][0..511] into smem (L2 reads, L1 stale) ----
        const float* hsrc = g_h[t & 1];
        for (int it = tid; it < 4096; it += 128) {
            int b = it >> 7, kq = it & 127;
            float4 v = __ldcg((const float4*)&hsrc[(size_t)(b0g + b) * HH + (kq << 2)]);
            int base = b * 513 + (kq << 2);
            hs[base + 0] = v.x; hs[base + 1] = v.y;
            hs[base + 2] = v.z; hs[base + 3] = v.w;
        }
        __syncthreads();

        // ---- GEMM: rec[32][48] = h[32][512] @ ws[512][48] ----
        float acc[4][3] = {};
#pragma unroll 8
        for (int k = 0; k < 512; ++k) {
            float w0 = ws[k * 48 + c0 + 0];
            float w1 = ws[k * 48 + c0 + 1];
            float w2 = ws[k * 48 + c0 + 2];
#pragma unroll
            for (int i = 0; i < 4; ++i) {
                float a = hs[(r0 + i) * 513 + k];
                acc[i][0] += a * w0;
                acc[i][1] += a * w1;
                acc[i][2] += a * w2;
            }
        }
#pragma unroll
        for (int i = 0; i < 4; ++i)
#pragma unroll
            for (int j = 0; j < 3; ++j)
                recs[(r0 + i) * 49 + c0 + j] = acc[i][j] + brs[c0 + j];
        __syncthreads();

        // ---- gates + state update for this CTA's 32x16 elements ----
        float* hdst = g_h[(t + 1) & 1];
        float* yout = isLast ? dout : (float*)g_y;
        for (int idx = tid; idx < 512; idx += 128) {
            int b = idx >> 4, c = idx & 15;
            int gb = b0g + b, gc = c0g + c;
            size_t xb = ((size_t)gb * TT + t) * H3;
            float xz = g_xp[xb + gc];
            float xr = g_xp[xb + HH + gc];
            float xh = g_xp[xb + 2 * HH + gc];
            float rz = recs[b * 49 + c];
            float rr = recs[b * 49 + 16 + c];
            float rh = recs[b * 49 + 32 + c];
            float z = 1.0f / (1.0f + expf(-(xz + rz)));
            float r = 1.0f / (1.0f + expf(-(xr + rr)));
            float hh = tanhf(xh + r * rh);
            float hold = hs[b * 513 + gc];
            float hn = z * hold + (1.0f - z) * hh;
            hdst[(size_t)gb * HH + gc] = hn;
            yout[((size_t)gb * TT + t) * HH + gc] = hn;
        }

        // ---- arrive ----
        __threadfence();
        __syncthreads();
        if (tid == 0) atomicAdd(&g_bar[g], 1u);
    }
}

// ---------------- final state copy -------------------------------------------
__global__ void copy_h_k(float* dout, int out_size) {
    int i = blockIdx.x * blockDim.x + threadIdx.x;
    size_t off = (size_t)BB * TT * HH;
    if (i < BB * HH && (off + i) < (size_t)out_size)
        dout[off + i] = g_h[0][i];
}

// ---------------- launch ------------------------------------------------------
extern "C" void kernel_launch(void* const* d_in, const int* in_sizes, int n_in,
                              void* d_out, int out_size) {
    const float* x        = (const float*)d_in[0];   // [B,T,H]
    const float* kernels  = (const float*)d_in[1];   // [L,H,3H]
    const float* rkernels = (const float*)d_in[2];   // [L,H,3H]
    const float* biases   = (const float*)d_in[3];   // [L,2,3H]
    float* out = (float*)d_out;

    cudaFuncSetAttribute(gru_layer_k, cudaFuncAttributeMaxDynamicSharedMemorySize,
                         SMEM_FLOATS * (int)sizeof(float));

    init_k<<<(BB * HH + 255) / 256, 256>>>();

    dim3 pgrid(H3 / 64, (BB * TT) / 64);
    for (int l = 0; l < 3; ++l) {
        proj_k<<<pgrid, 256>>>(x,
                               kernels + (size_t)l * HH * H3,
                               biases + (size_t)l * 2 * H3,
                               l > 0);
        gru_layer_k<<<128, 128, SMEM_FLOATS * (int)sizeof(float)>>>(
            rkernels + (size_t)l * HH * H3,
            biases + (size_t)l * 2 * H3 + H3,
            out, l, (l == 2) ? 1 : 0);
    }
    copy_h_k<<<(BB * HH + 255) / 256, 256>>>(out, out_size);
}